// round 7
// baseline (speedup 1.0000x reference)
#include <cuda_runtime.h>
#include <cstdint>

// Problem constants (fixed by the reference setup).
constexpr int B  = 32;
constexpr int H  = 512;
constexpr int W  = 512;
constexpr int HW = H * W;                  // 2^18 per channel plane
constexpr int NPIX = B * HW;               // 8,388,608 pixels
constexpr int K  = 4;                      // batches per thread
constexpr int THREADS = 256;
constexpr int NTHREADS_TOTAL = NPIX / K;               // 2,097,152
constexpr int GRID = NTHREADS_TOTAL / THREADS;         // 8192 blocks
constexpr float INV_COUNT = 1.0f / (2.0f * (float)NPIX);

__device__ float g_partials[GRID];
__device__ int   g_count = 0;

// max 4 CTAs/SM -> 1024 threads/SM -> 64 regs/thread available.
__global__ __launch_bounds__(THREADS, 4)
void cyc_loss_fused(const float* __restrict__ fwd, const float* __restrict__ bwd,
                    float* __restrict__ out)
{
    const int t = blockIdx.x * THREADS + threadIdx.x;  // [0, 2^21)
    const int b_base = t >> 18;                        // [0,8)
    const int pix    = t & (HW - 1);                   // == y*W + x
    const int y      = pix >> 9;
    const int x      = pix & 511;

    // ---- Load all forward displacements (coalesced) ----
    float dxv[K], dyv[K];
#pragma unroll
    for (int k = 0; k < K; ++k) {
        const float* __restrict__ fw = fwd + (size_t)(b_base + (k << 3)) * 2 * HW;
        dxv[k] = __ldg(fw + pix);
        dyv[k] = __ldg(fw + HW + pix);
    }

    // ---- Compute all tap addresses ----
    float wxv[K], wyv[K];
    int i00v[K], i01v[K], i10v[K], i11v[K];
#pragma unroll
    for (int k = 0; k < K; ++k) {
        const float gx = fminf(fmaxf((float)x + dxv[k], 0.0f), (float)(W - 1));
        const float gy = fminf(fmaxf((float)y + dyv[k], 0.0f), (float)(H - 1));
        const int x0 = __float2int_rd(gx);
        const int y0 = __float2int_rd(gy);
        wxv[k] = gx - (float)x0;
        wyv[k] = gy - (float)y0;
        const int x1 = min(x0 + 1, W - 1);
        const int y1 = min(y0 + 1, H - 1);
        const int r0 = y0 << 9;
        const int r1 = y1 << 9;
        i00v[k] = r0 + x0;  i01v[k] = r0 + x1;
        i10v[k] = r1 + x0;  i11v[k] = r1 + x1;
    }

    // ---- Issue ALL 32 gather loads back-to-back (MLP) ----
    float a00[K], a01[K], a10[K], a11[K];
    float b00[K], b01[K], b10[K], b11[K];
#pragma unroll
    for (int k = 0; k < K; ++k) {
        const float* __restrict__ c0 = bwd + (size_t)(b_base + (k << 3)) * 2 * HW;
        a00[k] = __ldg(c0 + i00v[k]);
        a01[k] = __ldg(c0 + i01v[k]);
        a10[k] = __ldg(c0 + i10v[k]);
        a11[k] = __ldg(c0 + i11v[k]);
    }
#pragma unroll
    for (int k = 0; k < K; ++k) {
        const float* __restrict__ c1 = bwd + (size_t)(b_base + (k << 3)) * 2 * HW + HW;
        b00[k] = __ldg(c1 + i00v[k]);
        b01[k] = __ldg(c1 + i01v[k]);
        b10[k] = __ldg(c1 + i10v[k]);
        b11[k] = __ldg(c1 + i11v[k]);
    }

    // ---- Math ----
    float acc = 0.0f;
#pragma unroll
    for (int k = 0; k < K; ++k) {
        const float wx = wxv[k];
        const float wy = wyv[k];
        const float top0 = fmaf(wx, a01[k] - a00[k], a00[k]);
        const float bot0 = fmaf(wx, a11[k] - a10[k], a10[k]);
        const float s0   = fmaf(wy, bot0 - top0, top0);
        const float top1 = fmaf(wx, b01[k] - b00[k], b00[k]);
        const float bot1 = fmaf(wx, b11[k] - b10[k], b10[k]);
        const float s1   = fmaf(wy, bot1 - top1, top1);
        const float r0 = dxv[k] + s0;
        const float r1 = dyv[k] + s1;
        acc = fmaf(r0, r0, acc);
        acc = fmaf(r1, r1, acc);
    }

    // ---- Block reduction (deterministic tree) ----
    __shared__ float warp_sums[THREADS / 32];
#pragma unroll
    for (int off = 16; off > 0; off >>= 1)
        acc += __shfl_xor_sync(0xFFFFFFFFu, acc, off);

    const int lane = threadIdx.x & 31;
    const int wid  = threadIdx.x >> 5;
    if (lane == 0) warp_sums[wid] = acc;
    __syncthreads();

    __shared__ bool is_last;
    if (wid == 0) {
        float v = (lane < THREADS / 32) ? warp_sums[lane] : 0.0f;
#pragma unroll
        for (int off = 4; off > 0; off >>= 1)
            v += __shfl_xor_sync(0xFFFFFFFFu, v, off);
        if (lane == 0) {
            __stcg(&g_partials[blockIdx.x], v);
            __threadfence();
            const int prev = atomicAdd(&g_count, 1);
            is_last = (prev == GRID - 1);
        }
    }
    __syncthreads();

    // ---- Last block: final reduction (fixed order -> deterministic) ----
    if (is_last) {
        float v = 0.0f;
        for (int i = threadIdx.x; i < GRID; i += THREADS)
            v += __ldcg(&g_partials[i]);

#pragma unroll
        for (int off = 16; off > 0; off >>= 1)
            v += __shfl_xor_sync(0xFFFFFFFFu, v, off);
        if (lane == 0) warp_sums[wid] = v;
        __syncthreads();

        if (wid == 0) {
            float s = (lane < THREADS / 32) ? warp_sums[lane] : 0.0f;
#pragma unroll
            for (int off = 4; off > 0; off >>= 1)
                s += __shfl_xor_sync(0xFFFFFFFFu, s, off);
            if (lane == 0) {
                out[0] = s * INV_COUNT;
                g_count = 0;
            }
        }
    }
}

extern "C" void kernel_launch(void* const* d_in, const int* in_sizes, int n_in,
                              void* d_out, int out_size)
{
    const float* fwd = (const float*)d_in[0];   // forward_disp  (B,2,H,W) fp32
    const float* bwd = (const float*)d_in[1];   // backward_disp (B,2,H,W) fp32
    float* out = (float*)d_out;

    cyc_loss_fused<<<GRID, THREADS>>>(fwd, bwd, out);
}